// round 3
// baseline (speedup 1.0000x reference)
#include <cuda_runtime.h>

#define Bn 8
#define Tn 8192
#define Dn 512
#define Mn 512
#define CH 16
#define NCH (Tn/CH)        // 512 chunks
#define SCH 512
#define NSC (Tn/SCH)       // 16 superchunks
#define CPS (SCH/CH)       // 32 chunks per superchunk

// Scratch (static device arrays: no dynamic allocation allowed)
__device__ float g_chunk[Bn*NCH*Dn];          // 8 MB: exclusive prefix (within superchunk) at chunk starts
__device__ float g_super[Bn*NSC*Dn];          // 256 KB: superchunk totals -> exclusive scanned
__device__ float g_mean[(size_t)Bn*Mn*Dn];    // 8 MB: segment means
__device__ float g_ffw[Mn*Dn];                // 1 MB: ff @ W_tail + bias

// ---------------------------------------------------------------------------
// Pass 1: per (b, superchunk) streaming scan. Writes chunk-granular exclusive
// prefixes and the superchunk total. Reads frame_emb exactly once (134 MB).
// ---------------------------------------------------------------------------
__global__ void k_chunkscan(const float* __restrict__ fe) {
    int blk = blockIdx.x;                 // b*NSC + sc, 128 blocks
    int b  = blk / NSC;
    int sc = blk - b * NSC;
    int d  = threadIdx.x * 4;             // 128 threads x float4 = 512 dims
    const float* src = fe + ((size_t)b*Tn + (size_t)sc*SCH)*Dn + d;
    float* cdst = g_chunk + ((size_t)b*NCH + (size_t)sc*CPS)*Dn + d;
    float4 acc = make_float4(0.f, 0.f, 0.f, 0.f);
    for (int c = 0; c < CPS; ++c) {
        *(float4*)(cdst + (size_t)c*Dn) = acc;   // exclusive prefix at chunk start
        #pragma unroll
        for (int r = 0; r < CH; ++r) {
            float4 v = *(const float4*)(src + (size_t)(c*CH + r)*Dn);
            acc.x += v.x; acc.y += v.y; acc.z += v.z; acc.w += v.w;
        }
    }
    *(float4*)(g_super + ((size_t)b*NSC + sc)*Dn + d) = acc;  // superchunk total
}

// ---------------------------------------------------------------------------
// Pass 2: exclusive scan of 16 superchunk totals per (b, d). Tiny.
// ---------------------------------------------------------------------------
__global__ void k_superscan() {
    int b = blockIdx.x;
    int d = threadIdx.x * 4;
    float* p = g_super + (size_t)b*NSC*Dn + d;
    float4 acc = make_float4(0.f, 0.f, 0.f, 0.f);
    #pragma unroll
    for (int s = 0; s < NSC; ++s) {
        float4 v = *(float4*)(p + (size_t)s*Dn);
        *(float4*)(p + (size_t)s*Dn) = acc;
        acc.x += v.x; acc.y += v.y; acc.z += v.z; acc.w += v.w;
    }
}

// Coarse prefix (super + chunk levels only) for boundary t; residual rows
// handled by the caller so both boundaries' loads can overlap.
__device__ __forceinline__ float4 coarseF(int b, int t, int d, int& c_out, int& n_out) {
    float4 r = make_float4(0.f, 0.f, 0.f, 0.f);
    c_out = 0; n_out = 0;
    if (t == 0) return r;
    int c = t / CH; if (c > NCH - 1) c = NCH - 1;   // t == Tn -> last chunk, 16 raw rows
    int sc = c / CPS;
    float4 su = *(const float4*)(g_super + ((size_t)b*NSC + sc)*Dn + d);
    float4 cp = *(const float4*)(g_chunk + ((size_t)b*NCH + c)*Dn + d);
    r.x = su.x + cp.x; r.y = su.y + cp.y; r.z = su.z + cp.z; r.w = su.w + cp.w;
    c_out = c;
    n_out = t - c*CH;                                // 0..16 raw rows
    return r;
}

// ---------------------------------------------------------------------------
// Pass 3: per (b, m) gather -> segment mean row.
// beat_bounds is int32 (the reference's .astype(jnp.int64) materializes as
// int32 under default JAX x64-disabled config).
// ---------------------------------------------------------------------------
__global__ void k_gather(const float* __restrict__ fe, const int* __restrict__ bb) {
    int bm = blockIdx.x;                  // 4096 blocks
    int b  = bm >> 9;                     // / Mn
    int s0 = bb[2*bm + 0];
    int e0 = bb[2*bm + 1];
    int s = s0 < 0 ? 0 : (s0 > (Tn-1) ? (Tn-1) : s0);
    int e = e0 < Tn ? e0 : Tn;
    if (e < s + 1) e = s + 1;
    int d = threadIdx.x * 4;

    int cs, ns, ce, ne;
    float4 Fs = coarseF(b, s, d, cs, ns);
    float4 Fe = coarseF(b, e, d, ce, ne);

    // Residual rows: interleave both streams to raise MLP.
    const float* rowS = fe + ((size_t)b*Tn + (size_t)cs*CH)*Dn + d;
    const float* rowE = fe + ((size_t)b*Tn + (size_t)ce*CH)*Dn + d;
    int nmax = ns > ne ? ns : ne;
    for (int i = 0; i < nmax; ++i) {
        if (i < ns) {
            float4 v = *(const float4*)(rowS + (size_t)i*Dn);
            Fs.x += v.x; Fs.y += v.y; Fs.z += v.z; Fs.w += v.w;
        }
        if (i < ne) {
            float4 v = *(const float4*)(rowE + (size_t)i*Dn);
            Fe.x += v.x; Fe.y += v.y; Fe.z += v.z; Fe.w += v.w;
        }
    }

    float inv = 1.0f / (float)(e - s);
    float4 o;
    o.x = (Fe.x - Fs.x) * inv;
    o.y = (Fe.y - Fs.y) * inv;
    o.z = (Fe.z - Fs.z) * inv;
    o.w = (Fe.w - Fs.w) * inv;
    *(float4*)(g_mean + (size_t)bm*Dn + d) = o;
}

// ---------------------------------------------------------------------------
// Pass 4: ffw[m, :] = fourier(m) @ W[512:544, :] + bias. One block per m.
// ---------------------------------------------------------------------------
__global__ void k_ffw(const float* __restrict__ W, const float* __restrict__ bias) {
    __shared__ float ff[32];
    int m = blockIdx.x;
    if (threadIdx.x < 32) {
        int j = threadIdx.x;
        float pos = (float)m / (float)(Mn - 1);
        pos = fminf(fmaxf(pos, 0.f), 1.f);
        float freq = expf((float)(j & 15) * 0.46051701859880913f);  // log(1000)/15
        float ang = pos * freq;
        ff[j] = (j < 16) ? sinf(ang) : cosf(ang);
    }
    __syncthreads();
    int n = threadIdx.x * 4;
    float4 acc = *(const float4*)(bias + n);
    #pragma unroll
    for (int j = 0; j < 32; ++j) {
        float f = ff[j];
        float4 w = *(const float4*)(W + (size_t)(Dn + j)*Dn + n);
        acc.x += f * w.x; acc.y += f * w.y; acc.z += f * w.z; acc.w += f * w.w;
    }
    *(float4*)(g_ffw + (size_t)m*Dn + n) = acc;
}

// ---------------------------------------------------------------------------
// Pass 5: GEMM C[4096,512] = g_mean @ W[0:512,:] + g_ffw[r&511,:]
// fp32, packed f32x2 FMA (sm_10x). BM=BN=128, BK=8, 256 threads, 8x8/thread
// with row-pair accumulators (loaded straight from SMEM as ulonglong2).
// ---------------------------------------------------------------------------
#define BM 128
#define BN 128
#define BK 8

#define FMA2(d_, a_, b_, c_) \
    asm("fma.rn.f32x2 %0, %1, %2, %3;" : "=l"(d_) : "l"(a_), "l"(b_), "l"(c_))
#define DUPF(d_, f_) \
    asm("mov.b64 %0, {%1, %1};" : "=l"(d_) : "f"(f_))

__global__ __launch_bounds__(256) void k_gemm(const float* __restrict__ W,
                                              float* __restrict__ C) {
    __shared__ __align__(16) float As[BK][BM];   // [k][m]
    __shared__ __align__(16) float Bs[BK][BN];   // [k][n]

    int tid = threadIdx.x;
    int tx = tid & 15;          // col group
    int ty = tid >> 4;          // row group
    int rowBase = blockIdx.y * BM;
    int colBase = blockIdx.x * BN;

    // global load mappings
    int a_row = tid >> 1;             // 0..127
    int a_k   = (tid & 1) * 4;        // 0 or 4
    int b_row = tid >> 5;             // 0..7
    int b_col = (tid & 31) * 4;       // 0..124

    const float* Aptr = g_mean + (size_t)(rowBase + a_row)*Dn + a_k;
    const float* Bptr = W + (size_t)b_row*Dn + colBase + b_col;

    unsigned long long acc[4][8];
    #pragma unroll
    for (int p = 0; p < 4; ++p)
        #pragma unroll
        for (int j = 0; j < 8; ++j) acc[p][j] = 0ULL;

    for (int kt = 0; kt < Dn; kt += BK) {
        float4 av = *(const float4*)(Aptr + kt);
        float4 bv = *(const float4*)(Bptr + (size_t)kt*Dn);
        __syncthreads();
        As[a_k + 0][a_row] = av.x;
        As[a_k + 1][a_row] = av.y;
        As[a_k + 2][a_row] = av.z;
        As[a_k + 3][a_row] = av.w;
        *(float4*)(&Bs[b_row][b_col]) = bv;
        __syncthreads();

        #pragma unroll
        for (int k = 0; k < BK; ++k) {
            ulonglong2 aA = *(const ulonglong2*)(&As[k][ty*8 + 0]); // pairs (m0,m1),(m2,m3)
            ulonglong2 aB = *(const ulonglong2*)(&As[k][ty*8 + 4]); // pairs (m4,m5),(m6,m7)
            float4 b0 = *(const float4*)(&Bs[k][tx*8 + 0]);
            float4 b1 = *(const float4*)(&Bs[k][tx*8 + 4]);
            unsigned long long ap[4];
            ap[0] = aA.x; ap[1] = aA.y; ap[2] = aB.x; ap[3] = aB.y;
            unsigned long long bd[8];
            DUPF(bd[0], b0.x); DUPF(bd[1], b0.y); DUPF(bd[2], b0.z); DUPF(bd[3], b0.w);
            DUPF(bd[4], b1.x); DUPF(bd[5], b1.y); DUPF(bd[6], b1.z); DUPF(bd[7], b1.w);
            #pragma unroll
            for (int p = 0; p < 4; ++p)
                #pragma unroll
                for (int j = 0; j < 8; ++j)
                    FMA2(acc[p][j], ap[p], bd[j], acc[p][j]);
        }
    }

    // epilogue: add ffw[r & 511, :] and store
    int rBase = rowBase + ty*8;
    int col = colBase + tx*8;
    #pragma unroll
    for (int p = 0; p < 4; ++p) {
        int r0 = rBase + 2*p;
        int m0 = r0 & (Mn - 1);
        int m1 = (r0 + 1) & (Mn - 1);
        float2 v[8];
        #pragma unroll
        for (int j = 0; j < 8; ++j) v[j] = *reinterpret_cast<float2*>(&acc[p][j]);
        float4 fa = *(const float4*)(g_ffw + (size_t)m0*Dn + col);
        float4 fb = *(const float4*)(g_ffw + (size_t)m0*Dn + col + 4);
        float4 ga = *(const float4*)(g_ffw + (size_t)m1*Dn + col);
        float4 gb = *(const float4*)(g_ffw + (size_t)m1*Dn + col + 4);
        float4 o;
        o = make_float4(v[0].x + fa.x, v[1].x + fa.y, v[2].x + fa.z, v[3].x + fa.w);
        *(float4*)(C + (size_t)r0*Dn + col) = o;
        o = make_float4(v[4].x + fb.x, v[5].x + fb.y, v[6].x + fb.z, v[7].x + fb.w);
        *(float4*)(C + (size_t)r0*Dn + col + 4) = o;
        o = make_float4(v[0].y + ga.x, v[1].y + ga.y, v[2].y + ga.z, v[3].y + ga.w);
        *(float4*)(C + (size_t)(r0+1)*Dn + col) = o;
        o = make_float4(v[4].y + gb.x, v[5].y + gb.y, v[6].y + gb.z, v[7].y + gb.w);
        *(float4*)(C + (size_t)(r0+1)*Dn + col + 4) = o;
    }
}

extern "C" void kernel_launch(void* const* d_in, const int* in_sizes, int n_in,
                              void* d_out, int out_size) {
    (void)in_sizes; (void)n_in; (void)out_size;
    const float* fe   = (const float*)d_in[0];      // [8, 8192, 512] f32
    const int*   bb   = (const int*)d_in[1];        // [8, 512, 2] int32 (jax x64 disabled)
    const float* W    = (const float*)d_in[2];      // [544, 512] f32
    const float* bias = (const float*)d_in[3];      // [512] f32
    float* out = (float*)d_out;                     // [8, 512, 512] f32

    k_chunkscan<<<Bn*NSC, 128>>>(fe);
    k_superscan<<<Bn, 128>>>();
    k_gather<<<Bn*Mn, 128>>>(fe, bb);
    k_ffw<<<Mn, 128>>>(W, bias);
    k_gemm<<<dim3(Dn/BN, (Bn*Mn)/BM), 256>>>(W, out);
}

// round 9
// speedup vs baseline: 1.4493x; 1.4493x over previous
#include <cuda_runtime.h>

#define Bn 8
#define Tn 8192
#define Dn 512
#define Mn 512
#define Kn 544              // 512 + POS_DIM
#define CH 8
#define NCH (Tn/CH)         // 1024 chunks
#define NSC 16              // superchunks
#define CPS (NCH/NSC)       // 64 chunks per superchunk

// Static scratch
__device__ float g_csum[Bn*NCH*Dn];           // 16 MB: chunk sums -> absolute exclusive prefixes (in-place)
__device__ float g_super[Bn*NSC*Dn];          // 256 KB: superchunk totals -> exclusive scanned
__device__ float g_mean[(size_t)Bn*Mn*Dn];    // 8 MB: segment means
__device__ float g_ff[Mn*32];                 // 64 KB: fourier features per beat index

// ---------------------------------------------------------------------------
// Pass 1: chunk sums. Fully parallel: 8192 CTAs, 8 independent loads/thread.
// ---------------------------------------------------------------------------
__global__ __launch_bounds__(128) void k_csum(const float* __restrict__ fe) {
    int blk = blockIdx.x;                 // b*NCH + c
    int b = blk >> 10;
    int c = blk & (NCH - 1);
    int d = threadIdx.x * 4;
    const float* src = fe + ((size_t)b*Tn + (size_t)c*CH)*Dn + d;
    float4 v0 = *(const float4*)(src + 0*Dn);
    float4 v1 = *(const float4*)(src + 1*Dn);
    float4 v2 = *(const float4*)(src + 2*Dn);
    float4 v3 = *(const float4*)(src + 3*Dn);
    float4 v4 = *(const float4*)(src + 4*Dn);
    float4 v5 = *(const float4*)(src + 5*Dn);
    float4 v6 = *(const float4*)(src + 6*Dn);
    float4 v7 = *(const float4*)(src + 7*Dn);
    float4 s;
    s.x = ((v0.x+v1.x)+(v2.x+v3.x)) + ((v4.x+v5.x)+(v6.x+v7.x));
    s.y = ((v0.y+v1.y)+(v2.y+v3.y)) + ((v4.y+v5.y)+(v6.y+v7.y));
    s.z = ((v0.z+v1.z)+(v2.z+v3.z)) + ((v4.z+v5.z)+(v6.z+v7.z));
    s.w = ((v0.w+v1.w)+(v2.w+v3.w)) + ((v4.w+v5.w)+(v6.w+v7.w));
    *(float4*)(g_csum + (size_t)blk*Dn + d) = s;
}

// ---------------------------------------------------------------------------
// Pass 2: superchunk totals (sum of 64 chunk sums). 128 CTAs.
// ---------------------------------------------------------------------------
__global__ __launch_bounds__(128) void k_ssum() {
    int blk = blockIdx.x;                 // b*NSC + sc
    int b  = blk >> 4;
    int sc = blk & 15;
    int d  = threadIdx.x * 4;
    const float* base = g_csum + ((size_t)b*NCH + (size_t)sc*CPS)*Dn + d;
    float4 a0 = make_float4(0,0,0,0), a1 = make_float4(0,0,0,0);
    #pragma unroll 8
    for (int c = 0; c < CPS; c += 2) {
        float4 v0 = *(const float4*)(base + (size_t)c*Dn);
        float4 v1 = *(const float4*)(base + (size_t)(c+1)*Dn);
        a0.x += v0.x; a0.y += v0.y; a0.z += v0.z; a0.w += v0.w;
        a1.x += v1.x; a1.y += v1.y; a1.z += v1.z; a1.w += v1.w;
    }
    float4 s = make_float4(a0.x+a1.x, a0.y+a1.y, a0.z+a1.z, a0.w+a1.w);
    *(float4*)(g_super + (size_t)blk*Dn + d) = s;
}

// ---------------------------------------------------------------------------
// Pass 3: exclusive scan of 16 superchunk totals per (b, d). Tiny.
// ---------------------------------------------------------------------------
__global__ __launch_bounds__(128) void k_superscan() {
    int b = blockIdx.x;
    int d = threadIdx.x * 4;
    float* p = g_super + (size_t)b*NSC*Dn + d;
    float4 acc = make_float4(0,0,0,0);
    #pragma unroll
    for (int s = 0; s < NSC; ++s) {
        float4 v = *(float4*)(p + (size_t)s*Dn);
        *(float4*)(p + (size_t)s*Dn) = acc;
        acc.x += v.x; acc.y += v.y; acc.z += v.z; acc.w += v.w;
    }
}

// ---------------------------------------------------------------------------
// Pass 4: in-place convert chunk sums -> ABSOLUTE exclusive prefixes.
// Batched (8-deep) loads keep MLP high despite the serial accumulate.
// ---------------------------------------------------------------------------
__global__ __launch_bounds__(128) void k_chunkprefix() {
    int blk = blockIdx.x;                 // b*NSC + sc
    int d  = threadIdx.x * 4;
    float* base = g_csum + (size_t)blk*CPS*Dn + d;
    float4 acc = *(const float4*)(g_super + (size_t)blk*Dn + d);
    #pragma unroll
    for (int g = 0; g < CPS/8; ++g) {
        float4 v[8];
        #pragma unroll
        for (int i = 0; i < 8; ++i)
            v[i] = *(const float4*)(base + (size_t)(g*8+i)*Dn);
        #pragma unroll
        for (int i = 0; i < 8; ++i) {
            *(float4*)(base + (size_t)(g*8+i)*Dn) = acc;
            acc.x += v[i].x; acc.y += v[i].y; acc.z += v[i].z; acc.w += v[i].w;
        }
    }
}

// ---------------------------------------------------------------------------
// Pass 5: gather segment means. beat_bounds is int32 (JAX x64 disabled).
// Absolute prefixes: F(t) = g_csum[b][t/CH] + raw rows [t/CH*CH, t).
// ---------------------------------------------------------------------------
__global__ __launch_bounds__(128) void k_gather(const float* __restrict__ fe,
                                                const int* __restrict__ bb) {
    int bm = blockIdx.x;                  // 4096 blocks
    int b  = bm >> 9;
    int s0 = bb[2*bm + 0];
    int e0 = bb[2*bm + 1];
    int s = s0 < 0 ? 0 : (s0 > (Tn-1) ? (Tn-1) : s0);
    int e = e0 < Tn ? e0 : Tn;
    if (e < s + 1) e = s + 1;
    int d = threadIdx.x * 4;

    int cs = s >> 3;                      // s < Tn so cs <= NCH-1
    int ce = e >> 3; if (ce > NCH - 1) ce = NCH - 1;
    int ns = s - cs*CH;                   // 0..7
    int ne = e - ce*CH;                   // 0..8

    float4 Fs = *(const float4*)(g_csum + ((size_t)b*NCH + cs)*Dn + d);
    float4 Fe = *(const float4*)(g_csum + ((size_t)b*NCH + ce)*Dn + d);

    const float* rowS = fe + ((size_t)b*Tn + (size_t)cs*CH)*Dn + d;
    const float* rowE = fe + ((size_t)b*Tn + (size_t)ce*CH)*Dn + d;
    int nmax = ns > ne ? ns : ne;
    for (int i = 0; i < nmax; ++i) {
        if (i < ns) {
            float4 v = *(const float4*)(rowS + (size_t)i*Dn);
            Fs.x += v.x; Fs.y += v.y; Fs.z += v.z; Fs.w += v.w;
        }
        if (i < ne) {
            float4 v = *(const float4*)(rowE + (size_t)i*Dn);
            Fe.x += v.x; Fe.y += v.y; Fe.z += v.z; Fe.w += v.w;
        }
    }

    float inv = 1.0f / (float)(e - s);
    float4 o;
    o.x = (Fe.x - Fs.x) * inv;
    o.y = (Fe.y - Fs.y) * inv;
    o.z = (Fe.z - Fs.z) * inv;
    o.w = (Fe.w - Fs.w) * inv;
    *(float4*)(g_mean + (size_t)bm*Dn + d) = o;
}

// ---------------------------------------------------------------------------
// Pass 6: fourier feature table g_ff[m][0..31]. Trivial.
// ---------------------------------------------------------------------------
__global__ void k_fftab() {
    int idx = blockIdx.x * blockDim.x + threadIdx.x;   // 0..16383
    if (idx >= Mn*32) return;
    int m = idx >> 5;
    int j = idx & 31;
    float pos = (float)m / (float)(Mn - 1);
    pos = fminf(fmaxf(pos, 0.f), 1.f);
    float freq = expf((float)(j & 15) * 0.46051701859880913f);  // log(1000)/15
    float ang = pos * freq;
    g_ff[idx] = (j < 16) ? sinf(ang) : cosf(ang);
}

// ---------------------------------------------------------------------------
// Pass 7: GEMM C[4096,512] = [g_mean | ff] @ W[0:544,:] + bias
// fp32 packed f32x2. BM=BN=128, BK=8, 256 threads, 8x8/thread.
// Conflict-free SMEM (As padded; B read at tx*4 / tx*4+64),
// register double-buffered global loads, bias folded into acc init.
// ---------------------------------------------------------------------------
#define BM 128
#define BN 128
#define BK 8
#define NT (Kn/BK)          // 68 K-tiles

#define FMA2(d_, a_, b_, c_) \
    asm("fma.rn.f32x2 %0, %1, %2, %3;" : "=l"(d_) : "l"(a_), "l"(b_), "l"(c_))
#define DUPF(d_, f_) \
    asm("mov.b64 %0, {%1, %1};" : "=l"(d_) : "f"(f_))

__device__ __forceinline__ float4 loadA_g(int row, int kk) {
    if (kk < Dn) return *(const float4*)(g_mean + (size_t)row*Dn + kk);
    return *(const float4*)(g_ff + (size_t)(row & (Mn-1))*32 + (kk - Dn));
}

__global__ __launch_bounds__(256) void k_gemm(const float* __restrict__ W,
                                              const float* __restrict__ bias,
                                              float* __restrict__ C) {
    __shared__ __align__(16) float As[BK][BM + 4];   // padded: conflict-free STS
    __shared__ __align__(16) float Bs[BK][BN];

    int tid = threadIdx.x;
    int tx = tid & 15;          // col group: cols tx*4 and tx*4+64
    int ty = tid >> 4;          // row group: rows ty*8 .. ty*8+7
    int rowBase = blockIdx.y * BM;
    int colBase = blockIdx.x * BN;

    int a_row = tid >> 1;             // 0..127
    int a_k   = (tid & 1) * 4;        // 0 or 4
    int b_row = tid >> 5;             // 0..7
    int b_col = (tid & 31) * 4;       // 0..124

    const float* Bgp = W + (size_t)b_row*Dn + colBase + b_col;

    // bias-initialized accumulators (both packed m-lanes share the column bias)
    unsigned long long acc[4][8];
    {
        float4 bs0 = *(const float4*)(bias + colBase + tx*4);
        float4 bs1 = *(const float4*)(bias + colBase + tx*4 + 64);
        unsigned long long bb0, bb1, bb2, bb3, bb4, bb5, bb6, bb7;
        DUPF(bb0, bs0.x); DUPF(bb1, bs0.y); DUPF(bb2, bs0.z); DUPF(bb3, bs0.w);
        DUPF(bb4, bs1.x); DUPF(bb5, bs1.y); DUPF(bb6, bs1.z); DUPF(bb7, bs1.w);
        #pragma unroll
        for (int p = 0; p < 4; ++p) {
            acc[p][0]=bb0; acc[p][1]=bb1; acc[p][2]=bb2; acc[p][3]=bb3;
            acc[p][4]=bb4; acc[p][5]=bb5; acc[p][6]=bb6; acc[p][7]=bb7;
        }
    }

    float4 av = loadA_g(rowBase + a_row, a_k);
    float4 bv = *(const float4*)(Bgp);

    for (int t = 0; t < NT; ++t) {
        __syncthreads();
        As[a_k + 0][a_row] = av.x;
        As[a_k + 1][a_row] = av.y;
        As[a_k + 2][a_row] = av.z;
        As[a_k + 3][a_row] = av.w;
        *(float4*)(&Bs[b_row][b_col]) = bv;
        __syncthreads();

        if (t + 1 < NT) {
            int kt = (t + 1) * BK;
            av = loadA_g(rowBase + a_row, kt + a_k);
            bv = *(const float4*)(Bgp + (size_t)kt*Dn);
        }

        #pragma unroll
        for (int k = 0; k < BK; ++k) {
            ulonglong2 aA = *(const ulonglong2*)(&As[k][ty*8 + 0]);
            ulonglong2 aB = *(const ulonglong2*)(&As[k][ty*8 + 4]);
            float4 b0 = *(const float4*)(&Bs[k][tx*4]);
            float4 b1 = *(const float4*)(&Bs[k][tx*4 + 64]);
            unsigned long long ap[4];
            ap[0] = aA.x; ap[1] = aA.y; ap[2] = aB.x; ap[3] = aB.y;
            unsigned long long bd[8];
            DUPF(bd[0], b0.x); DUPF(bd[1], b0.y); DUPF(bd[2], b0.z); DUPF(bd[3], b0.w);
            DUPF(bd[4], b1.x); DUPF(bd[5], b1.y); DUPF(bd[6], b1.z); DUPF(bd[7], b1.w);
            #pragma unroll
            for (int p = 0; p < 4; ++p)
                #pragma unroll
                for (int j = 0; j < 8; ++j)
                    FMA2(acc[p][j], ap[p], bd[j], acc[p][j]);
        }
    }

    // epilogue: acc[p][j] lanes = rows (ty*8+2p, ty*8+2p+1); cols tx*4(+64)
    int rBase = rowBase + ty*8;
    int col0 = colBase + tx*4;
    #pragma unroll
    for (int p = 0; p < 4; ++p) {
        int r0 = rBase + 2*p;
        float2 v[8];
        #pragma unroll
        for (int j = 0; j < 8; ++j) v[j] = *reinterpret_cast<float2*>(&acc[p][j]);
        float4 o;
        o = make_float4(v[0].x, v[1].x, v[2].x, v[3].x);
        *(float4*)(C + (size_t)r0*Dn + col0) = o;
        o = make_float4(v[4].x, v[5].x, v[6].x, v[7].x);
        *(float4*)(C + (size_t)r0*Dn + col0 + 64) = o;
        o = make_float4(v[0].y, v[1].y, v[2].y, v[3].y);
        *(float4*)(C + (size_t)(r0+1)*Dn + col0) = o;
        o = make_float4(v[4].y, v[5].y, v[6].y, v[7].y);
        *(float4*)(C + (size_t)(r0+1)*Dn + col0 + 64) = o;
    }
}

extern "C" void kernel_launch(void* const* d_in, const int* in_sizes, int n_in,
                              void* d_out, int out_size) {
    (void)in_sizes; (void)n_in; (void)out_size;
    const float* fe   = (const float*)d_in[0];      // [8, 8192, 512] f32
    const int*   bb   = (const int*)d_in[1];        // [8, 512, 2] int32
    const float* W    = (const float*)d_in[2];      // [544, 512] f32
    const float* bias = (const float*)d_in[3];      // [512] f32
    float* out = (float*)d_out;                     // [8, 512, 512] f32

    k_csum<<<Bn*NCH, 128>>>(fe);
    k_fftab<<<16, 1024>>>();
    k_ssum<<<Bn*NSC, 128>>>();
    k_superscan<<<Bn, 128>>>();
    k_chunkprefix<<<Bn*NSC, 128>>>();
    k_gather<<<Bn*Mn, 128>>>(fe, bb);
    k_gemm<<<dim3(Dn/BN, (Bn*Mn)/BM), 256>>>(W, bias, out);
}

// round 17
// speedup vs baseline: 2.1405x; 1.4769x over previous
#include <cuda_runtime.h>
#include <cuda_bf16.h>
#include <cstdint>

#define Bn 8
#define Tn 8192
#define Dn 512
#define Mn 512
#define KP 576              // K = 544 padded to 9*64 (pad cols stay zero)
#define KC 64
#define NCHUNK 9
#define CH 8
#define NCH (Tn/CH)         // 1024 chunks
#define NSC 16              // superchunks
#define CPS (NCH/NSC)       // 64 chunks per superchunk

// Static scratch (zero-initialized; K-pad columns are never written)
__device__ float g_csum[Bn*NCH*Dn];                 // 16.8 MB
__device__ float g_super[Bn*NSC*Dn];                // 256 KB
__device__ __nv_bfloat16 g_Ah[(size_t)Bn*Mn*KP];    // A hi: means + fourier, K-padded
__device__ __nv_bfloat16 g_Al[(size_t)Bn*Mn*KP];    // A lo
__device__ __nv_bfloat16 g_Wh[(size_t)Dn*KP];       // W^T hi, [n][k] K-contiguous
__device__ __nv_bfloat16 g_Wl[(size_t)Dn*KP];       // W^T lo

__device__ __forceinline__ void split_bf16(float x, __nv_bfloat16& h, __nv_bfloat16& l) {
    h = __float2bfloat16(x);
    l = __float2bfloat16(x - __bfloat162float(h));
}

// ---------------------------------------------------------------------------
// Pass 1: chunk sums. 8192 CTAs, 8 independent loads/thread.
// ---------------------------------------------------------------------------
__global__ __launch_bounds__(128) void k_csum(const float* __restrict__ fe) {
    int blk = blockIdx.x;
    int b = blk >> 10;
    int c = blk & (NCH - 1);
    int d = threadIdx.x * 4;
    const float* src = fe + ((size_t)b*Tn + (size_t)c*CH)*Dn + d;
    float4 v0 = *(const float4*)(src + 0*Dn);
    float4 v1 = *(const float4*)(src + 1*Dn);
    float4 v2 = *(const float4*)(src + 2*Dn);
    float4 v3 = *(const float4*)(src + 3*Dn);
    float4 v4 = *(const float4*)(src + 4*Dn);
    float4 v5 = *(const float4*)(src + 5*Dn);
    float4 v6 = *(const float4*)(src + 6*Dn);
    float4 v7 = *(const float4*)(src + 7*Dn);
    float4 s;
    s.x = ((v0.x+v1.x)+(v2.x+v3.x)) + ((v4.x+v5.x)+(v6.x+v7.x));
    s.y = ((v0.y+v1.y)+(v2.y+v3.y)) + ((v4.y+v5.y)+(v6.y+v7.y));
    s.z = ((v0.z+v1.z)+(v2.z+v3.z)) + ((v4.z+v5.z)+(v6.z+v7.z));
    s.w = ((v0.w+v1.w)+(v2.w+v3.w)) + ((v4.w+v5.w)+(v6.w+v7.w));
    *(float4*)(g_csum + (size_t)blk*Dn + d) = s;
}

// ---------------------------------------------------------------------------
// Pass 2: chunk sums -> LOCAL exclusive prefixes in-place + superchunk total.
// ---------------------------------------------------------------------------
__global__ __launch_bounds__(128) void k_scanlocal() {
    int blk = blockIdx.x;
    int d  = threadIdx.x * 4;
    float* base = g_csum + (size_t)blk*CPS*Dn + d;
    float4 acc = make_float4(0.f, 0.f, 0.f, 0.f);
    #pragma unroll
    for (int g = 0; g < CPS/8; ++g) {
        float4 v[8];
        #pragma unroll
        for (int i = 0; i < 8; ++i)
            v[i] = *(const float4*)(base + (size_t)(g*8+i)*Dn);
        #pragma unroll
        for (int i = 0; i < 8; ++i) {
            *(float4*)(base + (size_t)(g*8+i)*Dn) = acc;
            acc.x += v[i].x; acc.y += v[i].y; acc.z += v[i].z; acc.w += v[i].w;
        }
    }
    *(float4*)(g_super + (size_t)blk*Dn + d) = acc;
}

// ---------------------------------------------------------------------------
// Pass 3: exclusive scan of 16 superchunk totals per (b, d). MLP=16.
// ---------------------------------------------------------------------------
__global__ __launch_bounds__(128) void k_superscan() {
    int b = blockIdx.x;
    int d = threadIdx.x * 4;
    float* p = g_super + (size_t)b*NSC*Dn + d;
    float4 v[NSC];
    #pragma unroll
    for (int s = 0; s < NSC; ++s)
        v[s] = *(const float4*)(p + (size_t)s*Dn);
    float4 acc = make_float4(0.f, 0.f, 0.f, 0.f);
    #pragma unroll
    for (int s = 0; s < NSC; ++s) {
        float4 t = v[s];
        *(float4*)(p + (size_t)s*Dn) = acc;
        acc.x += t.x; acc.y += t.y; acc.z += t.z; acc.w += t.w;
    }
}

// ---------------------------------------------------------------------------
// Pass 4: gather segment means -> split-bf16 A (cols 0..511).
// ---------------------------------------------------------------------------
__global__ __launch_bounds__(128) void k_gather(const float* __restrict__ fe,
                                                const int* __restrict__ bb) {
    int bm = blockIdx.x;
    int b  = bm >> 9;
    int s0 = bb[2*bm + 0];
    int e0 = bb[2*bm + 1];
    int s = s0 < 0 ? 0 : (s0 > (Tn-1) ? (Tn-1) : s0);
    int e = e0 < Tn ? e0 : Tn;
    if (e < s + 1) e = s + 1;
    int d = threadIdx.x * 4;

    int cs = s >> 3;
    int ce = e >> 3; if (ce > NCH - 1) ce = NCH - 1;
    int ns = s - cs*CH;
    int ne = e - ce*CH;
    int scs = cs / CPS;
    int sce = ce / CPS;

    float4 Ls = *(const float4*)(g_csum + ((size_t)b*NCH + cs)*Dn + d);
    float4 Le = *(const float4*)(g_csum + ((size_t)b*NCH + ce)*Dn + d);
    float4 Ss = *(const float4*)(g_super + ((size_t)b*NSC + scs)*Dn + d);
    float4 Se = *(const float4*)(g_super + ((size_t)b*NSC + sce)*Dn + d);
    float4 Fs = make_float4(Ss.x + Ls.x, Ss.y + Ls.y, Ss.z + Ls.z, Ss.w + Ls.w);
    float4 Fe = make_float4(Se.x + Le.x, Se.y + Le.y, Se.z + Le.z, Se.w + Le.w);

    const float* rowS = fe + ((size_t)b*Tn + (size_t)cs*CH)*Dn + d;
    const float* rowE = fe + ((size_t)b*Tn + (size_t)ce*CH)*Dn + d;
    int nmax = ns > ne ? ns : ne;
    for (int i = 0; i < nmax; ++i) {
        if (i < ns) {
            float4 v = *(const float4*)(rowS + (size_t)i*Dn);
            Fs.x += v.x; Fs.y += v.y; Fs.z += v.z; Fs.w += v.w;
        }
        if (i < ne) {
            float4 v = *(const float4*)(rowE + (size_t)i*Dn);
            Fe.x += v.x; Fe.y += v.y; Fe.z += v.z; Fe.w += v.w;
        }
    }

    float inv = 1.0f / (float)(e - s);
    float ox = (Fe.x - Fs.x) * inv;
    float oy = (Fe.y - Fs.y) * inv;
    float oz = (Fe.z - Fs.z) * inv;
    float ow = (Fe.w - Fs.w) * inv;

    __nv_bfloat16 hx, lx, hy, ly, hz, lz, hw, lw;
    split_bf16(ox, hx, lx); split_bf16(oy, hy, ly);
    split_bf16(oz, hz, lz); split_bf16(ow, hw, lw);
    size_t off = (size_t)bm*KP + d;
    *(__nv_bfloat162*)(g_Ah + off)     = __nv_bfloat162(hx, hy);
    *(__nv_bfloat162*)(g_Ah + off + 2) = __nv_bfloat162(hz, hw);
    *(__nv_bfloat162*)(g_Al + off)     = __nv_bfloat162(lx, ly);
    *(__nv_bfloat162*)(g_Al + off + 2) = __nv_bfloat162(lz, lw);
}

// ---------------------------------------------------------------------------
// Pass 5: fourier features -> split-bf16 A cols 512..543 (all 4096 rows).
// ---------------------------------------------------------------------------
__global__ void k_fftab() {
    int idx = blockIdx.x * blockDim.x + threadIdx.x;
    if (idx >= Bn*Mn*32) return;
    int row = idx >> 5;
    int j = idx & 31;
    int m = row & (Mn - 1);
    float pos = (float)m / (float)(Mn - 1);
    pos = fminf(fmaxf(pos, 0.f), 1.f);
    float freq = expf((float)(j & 15) * 0.46051701859880913f);  // log(1000)/15
    float ang = pos * freq;
    float f = (j < 16) ? sinf(ang) : cosf(ang);
    __nv_bfloat16 h, l; split_bf16(f, h, l);
    g_Ah[(size_t)row*KP + Dn + j] = h;
    g_Al[(size_t)row*KP + Dn + j] = l;
}

// ---------------------------------------------------------------------------
// Pass 6: W[544,512] -> split-bf16 W^T [512][576] K-major (pad stays 0).
// ---------------------------------------------------------------------------
__global__ void k_wsplit(const float* __restrict__ W) {
    int idx = blockIdx.x * blockDim.x + threadIdx.x;   // 68*512 total
    if (idx >= 68*Dn) return;
    int kg = idx >> 9;
    int n  = idx & (Dn - 1);
    int k0 = kg * 8;
    __nv_bfloat16 h[8], l[8];
    #pragma unroll
    for (int i = 0; i < 8; ++i) {
        float w = W[(size_t)(k0 + i)*Dn + n];
        split_bf16(w, h[i], l[i]);
    }
    *(uint4*)(g_Wh + (size_t)n*KP + k0) = *(const uint4*)h;
    *(uint4*)(g_Wl + (size_t)n*KP + k0) = *(const uint4*)l;
}

// ---------------------------------------------------------------------------
// Pass 7: tensor-core GEMM via baseline mma.sync (m16n8k16 bf16, HMMA).
// C[4096,512] = A @ W^T + bias, 3-term split-bf16, fp32 accumulate.
// CTA 128x128 (256 thr, 8 warps 4x2; warp = 32x64 = 2 m-tiles x 8 n-tiles).
// SMEM tiles [128][72] bf16 (stride 72 -> conflict-free fragment LDS).
// ---------------------------------------------------------------------------
#define SSTR 72
#define TILE_B (128*SSTR*2)           // 18432 bytes per tile
#define OFF_AH 0
#define OFF_AL TILE_B
#define OFF_BH (2*TILE_B)
#define OFF_BL (3*TILE_B)
#define SMEM_TOTAL (4*TILE_B)         // 73728

#define MMA16816(d0,d1,d2,d3,a0,a1,a2,a3,b0,b1) \
    asm volatile("mma.sync.aligned.m16n8k16.row.col.f32.bf16.bf16.f32 " \
        "{%0,%1,%2,%3}, {%4,%5,%6,%7}, {%8,%9}, {%0,%1,%2,%3};" \
        : "+f"(d0), "+f"(d1), "+f"(d2), "+f"(d3) \
        : "r"(a0), "r"(a1), "r"(a2), "r"(a3), "r"(b0), "r"(b1))

__global__ __launch_bounds__(256) void k_gemm_mma(const float* __restrict__ bias,
                                                  float* __restrict__ C) {
    extern __shared__ __align__(16) char smem[];
    int tid = threadIdx.x;
    int wid = tid >> 5, lane = tid & 31;
    int g = lane >> 2, tg = lane & 3;
    int warpRow = (wid & 3) * 32;
    int warpCol = (wid >> 2) * 64;
    int rowBase = blockIdx.y * 128;
    int colBase = blockIdx.x * 128;

    float acc[2][8][4];
    #pragma unroll
    for (int mt = 0; mt < 2; ++mt)
        #pragma unroll
        for (int nt = 0; nt < 8; ++nt)
            #pragma unroll
            for (int i = 0; i < 4; ++i) acc[mt][nt][i] = 0.f;

    // global tile source pointers for this thread's copy slice
    int crow = tid >> 1;              // 0..127
    int chalf = (tid & 1) * 32;       // 0 or 32 (bf16 elems)
    const __nv_bfloat16* gAh = g_Ah + (size_t)(rowBase + crow)*KP + chalf;
    const __nv_bfloat16* gAl = g_Al + (size_t)(rowBase + crow)*KP + chalf;
    const __nv_bfloat16* gBh = g_Wh + (size_t)(colBase + crow)*KP + chalf;
    const __nv_bfloat16* gBl = g_Wl + (size_t)(colBase + crow)*KP + chalf;
    char* sdstA = smem + (size_t)crow*SSTR*2 + chalf*2;

    for (int c = 0; c < NCHUNK; ++c) {
        int ko = c * KC;
        __syncthreads();
        #pragma unroll
        for (int i = 0; i < 4; ++i) {
            uint4 va = *(const uint4*)(gAh + ko + i*8);
            uint4 vb = *(const uint4*)(gAl + ko + i*8);
            uint4 vc = *(const uint4*)(gBh + ko + i*8);
            uint4 vd = *(const uint4*)(gBl + ko + i*8);
            *(uint4*)(sdstA + OFF_AH + i*16) = va;
            *(uint4*)(sdstA + OFF_AL + i*16) = vb;
            *(uint4*)(sdstA + OFF_BH + i*16) = vc;
            *(uint4*)(sdstA + OFF_BL + i*16) = vd;
        }
        __syncthreads();

        #pragma unroll
        for (int kk = 0; kk < 4; ++kk) {
            int kcol = kk*16 + tg*2;
            // A fragments: [mt][4] for hi and lo
            uint32_t aH[2][4], aL[2][4];
            #pragma unroll
            for (int mt = 0; mt < 2; ++mt) {
                int r0 = warpRow + mt*16 + g;
                size_t o00 = ((size_t)r0*SSTR + kcol)*2;
                size_t o10 = ((size_t)(r0+8)*SSTR + kcol)*2;
                aH[mt][0] = *(const uint32_t*)(smem + OFF_AH + o00);
                aH[mt][1] = *(const uint32_t*)(smem + OFF_AH + o10);
                aH[mt][2] = *(const uint32_t*)(smem + OFF_AH + o00 + 16);
                aH[mt][3] = *(const uint32_t*)(smem + OFF_AH + o10 + 16);
                aL[mt][0] = *(const uint32_t*)(smem + OFF_AL + o00);
                aL[mt][1] = *(const uint32_t*)(smem + OFF_AL + o10);
                aL[mt][2] = *(const uint32_t*)(smem + OFF_AL + o00 + 16);
                aL[mt][3] = *(const uint32_t*)(smem + OFF_AL + o10 + 16);
            }
            #pragma unroll
            for (int nt = 0; nt < 8; ++nt) {
                int nrow = warpCol + nt*8 + g;
                size_t ob = ((size_t)nrow*SSTR + kcol)*2;
                uint32_t bH0 = *(const uint32_t*)(smem + OFF_BH + ob);
                uint32_t bH1 = *(const uint32_t*)(smem + OFF_BH + ob + 16);
                uint32_t bL0 = *(const uint32_t*)(smem + OFF_BL + ob);
                uint32_t bL1 = *(const uint32_t*)(smem + OFF_BL + ob + 16);
                #pragma unroll
                for (int mt = 0; mt < 2; ++mt) {
                    MMA16816(acc[mt][nt][0], acc[mt][nt][1], acc[mt][nt][2], acc[mt][nt][3],
                             aH[mt][0], aH[mt][1], aH[mt][2], aH[mt][3], bH0, bH1);
                    MMA16816(acc[mt][nt][0], acc[mt][nt][1], acc[mt][nt][2], acc[mt][nt][3],
                             aL[mt][0], aL[mt][1], aL[mt][2], aL[mt][3], bH0, bH1);
                    MMA16816(acc[mt][nt][0], acc[mt][nt][1], acc[mt][nt][2], acc[mt][nt][3],
                             aH[mt][0], aH[mt][1], aH[mt][2], aH[mt][3], bL0, bL1);
                }
            }
        }
    }

    // epilogue: c0=D[g][tg*2], c1=D[g][tg*2+1], c2=D[g+8][tg*2], c3=D[g+8][tg*2+1]
    #pragma unroll
    for (int nt = 0; nt < 8; ++nt) {
        int col = colBase + warpCol + nt*8 + tg*2;
        float2 bv = *(const float2*)(bias + col);
        #pragma unroll
        for (int mt = 0; mt < 2; ++mt) {
            int r0 = rowBase + warpRow + mt*16 + g;
            float2 o0, o1;
            o0.x = acc[mt][nt][0] + bv.x;
            o0.y = acc[mt][nt][1] + bv.y;
            o1.x = acc[mt][nt][2] + bv.x;
            o1.y = acc[mt][nt][3] + bv.y;
            *(float2*)(C + (size_t)r0*Dn + col)       = o0;
            *(float2*)(C + (size_t)(r0+8)*Dn + col)   = o1;
        }
    }
}

extern "C" void kernel_launch(void* const* d_in, const int* in_sizes, int n_in,
                              void* d_out, int out_size) {
    (void)in_sizes; (void)n_in; (void)out_size;
    const float* fe   = (const float*)d_in[0];      // [8, 8192, 512] f32
    const int*   bb   = (const int*)d_in[1];        // [8, 512, 2] int32
    const float* W    = (const float*)d_in[2];      // [544, 512] f32
    const float* bias = (const float*)d_in[3];      // [512] f32
    float* out = (float*)d_out;                     // [8, 512, 512] f32

    cudaFuncSetAttribute(k_gemm_mma, cudaFuncAttributeMaxDynamicSharedMemorySize,
                         SMEM_TOTAL);

    k_csum<<<Bn*NCH, 128>>>(fe);
    k_fftab<<<(Bn*Mn*32 + 255)/256, 256>>>();
    k_wsplit<<<(68*Dn + 255)/256, 256>>>(W);
    k_scanlocal<<<Bn*NSC, 128>>>();
    k_superscan<<<Bn, 128>>>();
    k_gather<<<Bn*Mn, 128>>>(fe, bb);
    k_gemm_mma<<<dim3(4, 32), 256, SMEM_TOTAL>>>(bias, out);
}